// round 13
// baseline (speedup 1.0000x reference)
#include <cuda_runtime.h>
#include <math.h>
#include <float.h>

#define BB  2
#define SS  512
#define DD  256
#define HH  8
#define DKK 32
#define NKK 16
#define TIV 16

#define Z_ELEMS (BB*SS*NKK*DD)   // 4194304
#define Q_ELEMS (BB*HH*SS*SS)    // 4194304

typedef unsigned long long ull;

// ---------------- f32x2 packed-math helpers ----------------
__device__ __forceinline__ ull ffma2(ull a, ull b, ull c){
    ull d;
    asm("fma.rn.f32x2 %0, %1, %2, %3;" : "=l"(d) : "l"(a), "l"(b), "l"(c));
    return d;
}
__device__ __forceinline__ ull pack2(float lo, float hi){
    ull d;
    asm("mov.b64 %0, {%1, %2};" : "=l"(d) : "f"(lo), "f"(hi));
    return d;
}
__device__ __forceinline__ void unpack2(ull v, float& lo, float& hi){
    asm("mov.b64 {%0, %1}, %2;" : "=f"(lo), "=f"(hi) : "l"(v));
}
__device__ __forceinline__ float fsqrt_fast(float x){
    float y;
    asm("sqrt.approx.f32 %0, %1;" : "=f"(y) : "f"(x));
    return y;
}

// ---------------- scratch ----------------
__device__ float g_WT [7*65536];            // transposed weights [w][kk][d]
__device__ float g_q1 [BB*HH*SS*DKK];
__device__ float g_q1T[BB*HH*DKK*SS];
__device__ float g_v1 [BB*HH*SS*DKK];
__device__ float g_att1[BB*SS*DD];
__device__ float g_p  [BB*SS*DD];
__device__ float g_k4 [BB*HH*SS*DKK];
__device__ float g_k4T[BB*HH*DKK*SS];
__device__ float g_v4 [BB*HH*SS*DKK];
__device__ float g_r4 [BB*NKK*HH*SS];
__device__ float g_P4 [BB*NKK*HH*SS];
__device__ float g_out4[BB*NKK*SS*DD];

// ---------------- helpers ----------------
__device__ __forceinline__ float warpMax(float v){
#pragma unroll
    for (int o = 16; o; o >>= 1) v = fmaxf(v, __shfl_xor_sync(0xffffffffu, v, o));
    return v;
}
__device__ __forceinline__ float warpSum(float v){
#pragma unroll
    for (int o = 16; o; o >>= 1) v += __shfl_xor_sync(0xffffffffu, v, o);
    return v;
}
__device__ __forceinline__ float halfwarpSum(float v){
#pragma unroll
    for (int o = 8; o; o >>= 1) v += __shfl_xor_sync(0xffffffffu, v, o);
    return v;
}
// inclusive scan of 512 floats in smem, 256 row-local threads
__device__ void rowScan512(float* sdata, float* swarp, int rtid){
    float a0 = sdata[2*rtid], a1 = sdata[2*rtid+1];
    float ts = a0 + a1;
    float v = ts;
#pragma unroll
    for (int o = 1; o < 32; o <<= 1){
        float n = __shfl_up_sync(0xffffffffu, v, o);
        if ((rtid & 31) >= o) v += n;
    }
    if ((rtid & 31) == 31) swarp[rtid >> 5] = v;
    __syncthreads();
    if (rtid < 8){
        float w = swarp[rtid];
#pragma unroll
        for (int o = 1; o < 8; o <<= 1){
            float n = __shfl_up_sync(0xffu, w, o);
            if (rtid >= o) w += n;
        }
        swarp[rtid] = w;
    }
    __syncthreads();
    float base = (rtid >= 32) ? swarp[(rtid >> 5) - 1] : 0.f;
    float excl = base + (v - ts);
    sdata[2*rtid]   = excl + a0;
    sdata[2*rtid+1] = excl + a0 + a1;
    __syncthreads();
}

// ---------------- weight transpose ----------------
__global__ void __launch_bounds__(256) transpose_w_kernel(
        const float* Wq1, const float* Wv1, const float* Wo1,
        const float* Wq4, const float* Wk4, const float* Wv4, const float* Wo4){
    int idx = blockIdx.x * 256 + threadIdx.x;
    int w = idx >> 16, e = idx & 65535;
    int d = e >> 8, kk = e & 255;
    const float* src;
    switch (w){
        case 0: src = Wq1; break;  case 1: src = Wv1; break;
        case 2: src = Wo1; break;  case 3: src = Wq4; break;
        case 4: src = Wk4; break;  case 5: src = Wv4; break;
        default: src = Wo4; break;
    }
    g_WT[w*65536 + kk*256 + d] = src[d*256 + kk];
}

// ---------------- proj3: merged 32x64 tile GEMM, double-buffered ----------------
__global__ void __launch_bounds__(256) proj3_kernel(
        const float* Xq, const float* Xse,
        const float* ba, const float* bbp, const float* bc, int single){
    __shared__ float Xs[32][34];
    __shared__ float Ws[32][68];
    int tid = threadIdx.x;
    int row0 = blockIdx.x * 32;
    int n0   = blockIdx.y * 64;
    int z = blockIdx.z;
    const float* X; const float* bias; int wsel, outsel;
    if (single){      X = g_p; bias = ba; wsel = 5; outsel = 3; }
    else if (z == 0){ X = Xq;  bias = ba; wsel = 4; outsel = 2; }
    else if (z == 1){ X = Xq;  bias = bbp; wsel = 0; outsel = 0; }
    else {            X = Xse; bias = bc; wsel = 1; outsel = 1; }
    const float* W = g_WT + (size_t)wsel*65536;

    int lr = tid >> 3;
    int lk = (tid & 7) * 4;
    int wk = tid >> 3;
    int wn = (tid & 7) * 8;

    int tc = tid & 15, tr = tid >> 4;
    ull acc[2][2] = {{0ull,0ull},{0ull,0ull}};

    float4 xv  = *(const float4*)&X[(size_t)(row0 + lr)*256 + lk];
    float4 wv0 = *(const float4*)&W[(size_t)wk*256 + n0 + wn];
    float4 wv1 = *(const float4*)&W[(size_t)wk*256 + n0 + wn + 4];

    for (int kc = 0; kc < 256; kc += 32){
        Xs[lk+0][lr] = xv.x; Xs[lk+1][lr] = xv.y;
        Xs[lk+2][lr] = xv.z; Xs[lk+3][lr] = xv.w;
        *(float4*)&Ws[wk][wn]   = wv0;
        *(float4*)&Ws[wk][wn+4] = wv1;
        __syncthreads();
        if (kc + 32 < 256){
            xv  = *(const float4*)&X[(size_t)(row0 + lr)*256 + kc + 32 + lk];
            wv0 = *(const float4*)&W[(size_t)(kc + 32 + wk)*256 + n0 + wn];
            wv1 = *(const float4*)&W[(size_t)(kc + 32 + wk)*256 + n0 + wn + 4];
        }
#pragma unroll
        for (int k = 0; k < 32; k++){
            float2 a = *(const float2*)&Xs[k][tr*2];
            float4 b = *(const float4*)&Ws[k][tc*4];
            ull b01 = pack2(b.x, b.y), b23 = pack2(b.z, b.w);
            ull a0 = pack2(a.x, a.x), a1 = pack2(a.y, a.y);
            acc[0][0] = ffma2(a0, b01, acc[0][0]);
            acc[0][1] = ffma2(a0, b23, acc[0][1]);
            acc[1][0] = ffma2(a1, b01, acc[1][0]);
            acc[1][1] = ffma2(a1, b23, acc[1][1]);
        }
        __syncthreads();
    }

    int n = n0 + tc*4;
    float4 bb = *(const float4*)&bias[n];
    int h = n >> 5, dk = n & 31;
    float* Yh; float* YT = nullptr;
    switch (outsel){
        case 0: Yh = g_q1; YT = g_q1T; break;
        case 1: Yh = g_v1; break;
        case 2: Yh = g_k4; YT = g_k4T; break;
        default: Yh = g_v4; break;
    }
#pragma unroll
    for (int q = 0; q < 2; q++){
        int row = row0 + tr*2 + q;
        int bidx = row >> 9, s = row & 511;
        float y0,y1,y2,y3;
        unpack2(acc[q][0], y0, y1);
        unpack2(acc[q][1], y2, y3);
        float4 v = make_float4(y0 + bb.x, y1 + bb.y, y2 + bb.z, y3 + bb.w);
        *(float4*)&Yh[(((size_t)(bidx*HH + h)*SS + s)*DKK + dk)] = v;
        if (YT){
            size_t tb = (size_t)(bidx*HH + h)*DKK;
            YT[(tb + dk + 0)*SS + s] = v.x;
            YT[(tb + dk + 1)*SS + s] = v.y;
            YT[(tb + dk + 2)*SS + s] = v.z;
            YT[(tb + dk + 3)*SS + s] = v.w;
        }
    }
}

// ---------------- epi2<RT>: (RT*16)x256 tile GEMM + residual + LayerNorm ----------------
template<int RT>
__global__ void __launch_bounds__(256) epi2_kernel(
        const float* resid, const float* lng, const float* lnb,
        int wsel, const float* bias, int mode, float* dst){
    constexpr int ROWS = RT*16;
    constexpr int XP = (RT == 4) ? 68 : 34;
    __shared__ float Xs[32][XP];
    __shared__ float Ws[32][264];
    int tid = threadIdx.x;
    int row0 = blockIdx.x * ROWS;
    const float* Xsrc = (mode == 0) ? g_att1 : g_out4;
    const float* W = g_WT + (size_t)wsel*65536;
    int tc = tid & 15, tr = tid >> 4;

    ull acc[RT][4][2];
#pragma unroll
    for (int r = 0; r < RT; r++)
#pragma unroll
        for (int cb = 0; cb < 4; cb++){ acc[r][cb][0] = 0ull; acc[r][cb][1] = 0ull; }

    int wk = tid >> 4;
    int wn = (tid & 15) * 16;

    for (int kc = 0; kc < 256; kc += 32){
        float4 x0, x1;
        int xr, xk;
        if (RT == 4){ xr = tid >> 2; xk = (tid & 3) * 8;
            x0 = *(const float4*)&Xsrc[(size_t)(row0 + xr)*256 + kc + xk];
            x1 = *(const float4*)&Xsrc[(size_t)(row0 + xr)*256 + kc + xk + 4];
        } else { xr = tid >> 3; xk = (tid & 7) * 4;
            x0 = *(const float4*)&Xsrc[(size_t)(row0 + xr)*256 + kc + xk];
        }
        float4 w0 = *(const float4*)&W[(size_t)(kc + wk)*256 + wn];
        float4 w1 = *(const float4*)&W[(size_t)(kc + wk)*256 + wn + 4];
        float4 w2 = *(const float4*)&W[(size_t)(kc + wk)*256 + wn + 8];
        float4 w3 = *(const float4*)&W[(size_t)(kc + wk)*256 + wn + 12];
        float4 w4 = *(const float4*)&W[(size_t)(kc + wk + 16)*256 + wn];
        float4 w5 = *(const float4*)&W[(size_t)(kc + wk + 16)*256 + wn + 4];
        float4 w6 = *(const float4*)&W[(size_t)(kc + wk + 16)*256 + wn + 8];
        float4 w7 = *(const float4*)&W[(size_t)(kc + wk + 16)*256 + wn + 12];
        Xs[xk+0][xr] = x0.x; Xs[xk+1][xr] = x0.y; Xs[xk+2][xr] = x0.z; Xs[xk+3][xr] = x0.w;
        if (RT == 4){
            Xs[xk+4][xr] = x1.x; Xs[xk+5][xr] = x1.y; Xs[xk+6][xr] = x1.z; Xs[xk+7][xr] = x1.w;
        }
        *(float4*)&Ws[wk][wn]      = w0;
        *(float4*)&Ws[wk][wn+4]    = w1;
        *(float4*)&Ws[wk][wn+8]    = w2;
        *(float4*)&Ws[wk][wn+12]   = w3;
        *(float4*)&Ws[wk+16][wn]   = w4;
        *(float4*)&Ws[wk+16][wn+4] = w5;
        *(float4*)&Ws[wk+16][wn+8] = w6;
        *(float4*)&Ws[wk+16][wn+12]= w7;
        __syncthreads();
#pragma unroll
        for (int k = 0; k < 32; k++){
            float a[RT];
            if (RT == 4){
                float4 av = *(const float4*)&Xs[k][tr*4];
                a[0]=av.x; a[1]=av.y; a[2]=av.z; a[3]=av.w;
            } else {
                float2 av = *(const float2*)&Xs[k][tr*2];
                a[0]=av.x; a[1]=av.y;
            }
            ull aa[RT];
#pragma unroll
            for (int r = 0; r < RT; r++) aa[r] = pack2(a[r], a[r]);
#pragma unroll
            for (int cb = 0; cb < 4; cb++){
                float4 b = *(const float4*)&Ws[k][cb*64 + tc*4];
                ull b01 = pack2(b.x, b.y), b23 = pack2(b.z, b.w);
#pragma unroll
                for (int r = 0; r < RT; r++){
                    acc[r][cb][0] = ffma2(aa[r], b01, acc[r][cb][0]);
                    acc[r][cb][1] = ffma2(aa[r], b23, acc[r][cb][1]);
                }
            }
        }
        __syncthreads();
    }

    int nb = tc*4;
    float4 bb[4], lg[4], lb[4];
#pragma unroll
    for (int cb = 0; cb < 4; cb++){
        bb[cb] = *(const float4*)&bias[cb*64 + nb];
        lg[cb] = *(const float4*)&lng [cb*64 + nb];
        lb[cb] = *(const float4*)&lnb [cb*64 + nb];
    }
#pragma unroll
    for (int q = 0; q < RT; q++){
        int row = row0 + tr*RT + q;
        float y[16];
#pragma unroll
        for (int cb = 0; cb < 4; cb++){
            float4 rv;
            if (mode == 0) rv = *(const float4*)&resid[(size_t)row*256 + cb*64 + nb];
            else { int kk = (row >> 9) & 15;
                   rv = *(const float4*)&resid[(size_t)kk*256 + cb*64 + nb]; }
            float a0,a1,a2,a3;
            unpack2(acc[q][cb][0], a0, a1);
            unpack2(acc[q][cb][1], a2, a3);
            y[cb*4+0] = a0 + bb[cb].x + rv.x;
            y[cb*4+1] = a1 + bb[cb].y + rv.y;
            y[cb*4+2] = a2 + bb[cb].z + rv.z;
            y[cb*4+3] = a3 + bb[cb].w + rv.w;
        }
        float s = 0.f;
#pragma unroll
        for (int e = 0; e < 16; e++) s += y[e];
        s = halfwarpSum(s);
        float mean = s * (1.f/256.f);
        float vs = 0.f;
#pragma unroll
        for (int e = 0; e < 16; e++){ float t = y[e] - mean; vs += t*t; }
        vs = halfwarpSum(vs);
        float inv = rsqrtf(vs*(1.f/256.f) + 1e-5f);
        size_t base;
        float* out;
        if (mode == 0){ base = (size_t)row*256; out = g_p; }
        else {
            int b = row >> 13, kk = (row >> 9) & 15, s2 = row & 511;
            base = ((size_t)(b*512 + s2)*16 + kk)*256; out = dst;
        }
#pragma unroll
        for (int cb = 0; cb < 4; cb++){
            float4 o;
            o.x = (y[cb*4+0]-mean)*inv*lg[cb].x + lb[cb].x;
            o.y = (y[cb*4+1]-mean)*inv*lg[cb].y + lb[cb].y;
            o.z = (y[cb*4+2]-mean)*inv*lg[cb].z + lb[cb].z;
            o.w = (y[cb*4+3]-mean)*inv*lg[cb].w + lb[cb].w;
            *(float4*)&out[base + cb*64 + nb] = o;
        }
    }
}

// ---------------- r4pre (fused knowproj): score rows + exp prefix sums ----------------
__global__ void __launch_bounds__(256) r4pre_kernel(const float* kp, const float* bq4){
    int idx = blockIdx.x;                 // (b*16+k)*8+h
    int h = idx & 7, bk = idx >> 3, b = bk >> 4, k = bk & 15;
    int tid = threadIdx.x;
    __shared__ float qv[DKK];
    __shared__ float red[8][33];
    __shared__ float sbuf[512];
    __shared__ float sred[8];
    {
        int d = tid & 31, gph = tid >> 5;
        const float* WT = g_WT + 3*65536;
        const float* kr = kp + k*256;
        float a = 0.f;
#pragma unroll 8
        for (int kk = gph*32; kk < gph*32 + 32; kk++)
            a += kr[kk] * WT[kk*256 + h*32 + d];
        red[gph][d] = a;
        __syncthreads();
        if (tid < 32){
            float s = bq4[h*32 + tid];
#pragma unroll
            for (int g2 = 0; g2 < 8; g2++) s += red[g2][tid];
            qv[tid] = s;
        }
        __syncthreads();
    }
    const float* kT = g_k4T + (size_t)(b*HH + h)*DKK*SS;
    int j0 = tid, j1 = tid + 256;
    float r0 = 0.f, r1 = 0.f;
#pragma unroll
    for (int d = 0; d < DKK; d++){
        float q = qv[d];
        r0 += q*kT[d*SS + j0];
        r1 += q*kT[d*SS + j1];
    }
    const float sc = 0.17677669529663687f;  // 1/sqrt(32)
    r0 *= sc; r1 *= sc;
    size_t rb = (size_t)idx*SS;
    g_r4[rb + j0] = r0; g_r4[rb + j1] = r1;
    sbuf[j0] = __expf(r0); sbuf[j1] = __expf(r1);
    __syncthreads();
    rowScan512(sbuf, sred, tid);
    g_P4[rb + j0] = sbuf[j0]; g_P4[rb + j1] = sbuf[j1];
}

// ---------------- attn1: 512 threads, warp-per-row, smem-stashed intermediates ----------
// grid (32 i-tiles of 16 rows, B*H).
__global__ void __launch_bounds__(512, 2) attn1_kernel(const float* gam, float* qsc){
    int tile = blockIdx.x;
    int bh   = blockIdx.y;          // b*8+h
    int b = bh >> 3, h = bh & 7;
    int tid = threadIdx.x;
    int lane = tid & 31, w = tid >> 5;   // w = 0..15 = row in tile
    int i0 = tile * TIV;

    __shared__ float q_s[TIV][DKK];
    __shared__ float p_s[SS][TIV + 2];

    q_s[w][lane] = g_q1[((size_t)bh*SS + i0 + w)*DKK + lane];
    __syncthreads();

    const float* kT = g_q1T + (size_t)bh*DKK*SS;   // kq_same
    float g = fabsf(gam[h]);
    const float sc = 0.17677669529663687f;

    int ii = w, i = i0 + ii;
    // pass A: scores + exp + running warp prefix; stash score r into p_s
    float PP[16];
    float S = 0.f;
#pragma unroll
    for (int c = 0; c < 16; c++){
        int j = lane + 32*c;
        float r = 0.f, e = 0.f;
        if (32*c <= i){
            if (j <= i){
#pragma unroll
                for (int d = 0; d < DKK; d++)
                    r += q_s[ii][d] * kT[d*SS + j];
                r *= sc;
                e = __expf(r);
            }
            p_s[j][ii] = r;
            float s1 = e;
#pragma unroll
            for (int o = 1; o < 32; o <<= 1){
                float n = __shfl_up_sync(0xffffffffu, s1, o);
                if (lane >= o) s1 += n;
            }
            PP[c] = S + s1;
            S += __shfl_sync(0xffffffffu, s1, 31);
        } else {
            PP[c] = S;
        }
    }
    float invZ = 1.f / S;
    // pass B: second-softmax numerators (read r from p_s, stash f)
    float Zp2 = 0.f;
#pragma unroll
    for (int c = 0; c < 16; c++){
        int j = lane + 32*c;
        float f = 0.f;
        if (j <= i){
            float r = p_s[j][ii];
            float tail = fmaxf(1.f - PP[c]*invZ, 0.f);
            float u = tail * (float)(i - j);
            float eff = fmaxf(__expf(-g*fsqrt_fast(u)), 1e-5f);
            f = __expf(r*eff);
        }
        p_s[j][ii] = f;
        Zp2 += f;
    }
    float inv2 = 1.f / warpSum(Zp2);
    // pass C: normalize, write qsc + p_s
    float* qrow = qsc + ((size_t)bh*SS + i)*SS;
#pragma unroll
    for (int c = 0; c < 16; c++){
        int j = lane + 32*c;
        float p = p_s[j][ii] * inv2;
        qrow[j]    = p;
        p_s[j][ii] = p;
    }
    __syncthreads();

    // PV: 8 warps, 2 rows x 32 d packed
    if (w < 8){
        int d0  = lane;
        int ii0 = w*2;
        ull acc = 0ull;
        const float* vcol = g_v1 + (size_t)bh*SS*DKK + d0;
        int tb = i0 + ii0 + 2;
        int jj = 0;
        for (; jj + 4 <= tb; jj += 4){
#pragma unroll
            for (int u2 = 0; u2 < 4; u2++){
                float v = vcol[(size_t)(jj+u2)*DKK];
                ull pp = *(const ull*)&p_s[jj+u2][ii0];
                acc = ffma2(pp, pack2(v, v), acc);
            }
        }
        for (; jj < tb; jj++){
            float v = vcol[(size_t)jj*DKK];
            ull pp = *(const ull*)&p_s[jj][ii0];
            acc = ffma2(pp, pack2(v, v), acc);
        }
        float a0, a1;
        unpack2(acc, a0, a1);
        float* ob = g_att1 + ((size_t)b*SS + i0 + ii0)*DD + h*DKK + d0;
        ob[0]  = a0;
        ob[DD] = a1;
    }
}

// ---------------- attn4: 512 threads, warp-per-row, j-split PV on 16 warps ----------
__global__ void __launch_bounds__(512, 2) attn4_kernel(const float* gam, float* ksc){
    int tile = blockIdx.x;
    int k    = blockIdx.y;
    int bh   = blockIdx.z;
    int b = bh >> 3, h = bh & 7;
    int tid = threadIdx.x;
    int lane = tid & 31, w = tid >> 5;   // 0..15
    int i0 = tile * TIV;

    __shared__ float r_s[SS];
    __shared__ float P_s[SS];
    __shared__ float p_s[SS][TIV + 2];
    __shared__ ull  red_s[8][33];

    size_t rb = ((size_t)((b*NKK + k)*HH + h)) * SS;
    if (tid < SS){
        r_s[tid] = g_r4[rb + tid];
        P_s[tid] = g_P4[rb + tid];
    }
    __syncthreads();

    float g = fabsf(gam[h]);
    size_t kbase0 = (((size_t)(b*HH + h)*SS + i0)*NKK + k)*SS;

    int ii = w, i = i0 + ii;
    float invS1 = (i > 0) ? 1.f / P_s[i-1] : 0.f;
    float fi = (float)i;
    float emax = 0.f, Zp = 0.f;
#pragma unroll
    for (int c = 0; c < 16; c++){
        float e = 0.f;
        int j = lane + 32*c;
        if (j < i){
            float r = r_s[j];
            float tail = fmaxf(1.f - P_s[j]*invS1, 0.f);
            float u = tail * (fi - (float)j);
            float eff = fmaxf(__expf(-g*fsqrt_fast(u)), 1e-5f);
            e = __expf(r*eff);
        }
        p_s[j][ii] = e;
        emax = fmaxf(emax, e);
        Zp += e;
    }
    float Z  = warpSum(Zp);
    float em = warpMax(emax);
    float C  = (Z > 0.f) ? fminf(Z/em, 5.f)/Z : 0.f;   // p = e*C (maxout folded)
    float* krow = ksc + kbase0 + (size_t)ii*(NKK*SS);
#pragma unroll
    for (int c = 0; c < 16; c++){
        int j = lane + 32*c;
        float p = p_s[j][ii]*C;
        krow[j]    = p;
        p_s[j][ii] = p;
    }
    __syncthreads();

    // PV: 16 warps; (pair, half) j-split; packed 2 rows x 32 d
    int pair = w & 7, half = w >> 3;
    int d0  = lane;
    int ii0 = pair*2;
    ull acc = 0ull;
    const float* vcol = g_v4 + (size_t)bh*SS*DKK + d0;
    int tb = i0 + ii0 + 2;
    for (int jj0 = half*64; jj0 < tb; jj0 += 128){
        int je = jj0 + 64; if (je > tb) je = tb;
#pragma unroll 4
        for (int jj = jj0; jj < je; jj++){
            float v = vcol[(size_t)jj*DKK];
            ull pp = *(const ull*)&p_s[jj][ii0];
            acc = ffma2(pp, pack2(v, v), acc);
        }
    }
    if (half == 1) red_s[pair][lane] = acc;
    __syncthreads();
    if (half == 0){
        float a0, a1, b0, b1;
        unpack2(acc, a0, a1);
        unpack2(red_s[pair][lane], b0, b1);
        a0 += b0; a1 += b1;
        float* ob = g_out4 + ((size_t)(b*NKK + k)*SS + i0 + ii0)*DD + h*DKK + d0;
        ob[0]  = a0;
        ob[DD] = a1;
    }
}

// ---------------- launch ----------------
extern "C" void kernel_launch(void* const* d_in, const int* in_sizes, int n_in,
                              void* d_out, int out_size){
    (void)in_sizes; (void)n_in; (void)out_size;
    const float* q_emb = (const float*)d_in[0];
    const float* s_emb = (const float*)d_in[1];
    const float* Wq1 = (const float*)d_in[5];
    const float* bq1 = (const float*)d_in[6];
    const float* Wv1 = (const float*)d_in[7];
    const float* bv1 = (const float*)d_in[8];
    const float* Wo1 = (const float*)d_in[9];
    const float* bo1 = (const float*)d_in[10];
    const float* gam1= (const float*)d_in[11];
    const float* ln1g= (const float*)d_in[12];
    const float* ln1b= (const float*)d_in[13];
    const float* Wq4 = (const float*)d_in[14];
    const float* bq4 = (const float*)d_in[15];
    const float* Wk4 = (const float*)d_in[16];
    const float* bk4 = (const float*)d_in[17];
    const float* Wv4 = (const float*)d_in[18];
    const float* bv4 = (const float*)d_in[19];
    const float* Wo4 = (const float*)d_in[20];
    const float* bo4 = (const float*)d_in[21];
    const float* gam4= (const float*)d_in[22];
    const float* ln4g= (const float*)d_in[23];
    const float* ln4b= (const float*)d_in[24];
    const float* knowp=(const float*)d_in[25];

    float* out  = (float*)d_out;
    float* z_out = out;                       // [B,S,NK*D]
    float* q_out = out + Z_ELEMS;             // [B,H,S,S]
    float* k_out = out + Z_ELEMS + Q_ELEMS;   // [B,H,S,NK,S]

    transpose_w_kernel<<<1792, 256>>>(Wq1, Wv1, Wo1, Wq4, Wk4, Wv4, Wo4);
    proj3_kernel<<<dim3(32,4,3), 256>>>(q_emb, s_emb, bk4, bq1, bv1, 0);  // k4+q1+v1
    r4pre_kernel<<<256, 256>>>(knowp, bq4);
    attn1_kernel<<<dim3(32, BB*HH), 512>>>(gam1, q_out);                  // 4th: profiled
    epi2_kernel<2><<<32, 256>>>(q_emb, ln1g, ln1b, 2, bo1, 0, nullptr);   // -> g_p
    proj3_kernel<<<dim3(32,4,1), 256>>>(nullptr, nullptr, bv4, nullptr, nullptr, 1); // v4
    attn4_kernel<<<dim3(32, NKK, BB*HH), 512>>>(gam4, k_out);
    epi2_kernel<4><<<256, 256>>>(knowp, ln4g, ln4b, 6, bo4, 1, z_out);    // -> z
}

// round 14
// speedup vs baseline: 1.1973x; 1.1973x over previous
#include <cuda_runtime.h>
#include <math.h>
#include <float.h>

#define BB  2
#define SS  512
#define DD  256
#define HH  8
#define DKK 32
#define NKK 16
#define TIV 16

#define Z_ELEMS (BB*SS*NKK*DD)   // 4194304
#define Q_ELEMS (BB*HH*SS*SS)    // 4194304

typedef unsigned long long ull;

// ---------------- f32x2 packed-math helpers ----------------
__device__ __forceinline__ ull ffma2(ull a, ull b, ull c){
    ull d;
    asm("fma.rn.f32x2 %0, %1, %2, %3;" : "=l"(d) : "l"(a), "l"(b), "l"(c));
    return d;
}
__device__ __forceinline__ ull pack2(float lo, float hi){
    ull d;
    asm("mov.b64 %0, {%1, %2};" : "=l"(d) : "f"(lo), "f"(hi));
    return d;
}
__device__ __forceinline__ void unpack2(ull v, float& lo, float& hi){
    asm("mov.b64 {%0, %1}, %2;" : "=f"(lo), "=f"(hi) : "l"(v));
}
__device__ __forceinline__ float fsqrt_fast(float x){
    float y;
    asm("sqrt.approx.f32 %0, %1;" : "=f"(y) : "f"(x));
    return y;
}

// ---------------- scratch ----------------
__device__ float g_WT [7*65536];            // transposed weights [w][kk][d]
__device__ float g_q1 [BB*HH*SS*DKK];
__device__ float g_q1T[BB*HH*DKK*SS];
__device__ float g_v1 [BB*HH*SS*DKK];
__device__ float g_att1[BB*SS*DD];
__device__ float g_p  [BB*SS*DD];
__device__ float g_k4 [BB*HH*SS*DKK];
__device__ float g_k4T[BB*HH*DKK*SS];
__device__ float g_v4 [BB*HH*SS*DKK];
__device__ float g_r4 [BB*NKK*HH*SS];
__device__ float g_P4 [BB*NKK*HH*SS];
__device__ float g_out4[BB*NKK*SS*DD];

// ---------------- helpers ----------------
__device__ __forceinline__ float warpMax(float v){
#pragma unroll
    for (int o = 16; o; o >>= 1) v = fmaxf(v, __shfl_xor_sync(0xffffffffu, v, o));
    return v;
}
__device__ __forceinline__ float warpSum(float v){
#pragma unroll
    for (int o = 16; o; o >>= 1) v += __shfl_xor_sync(0xffffffffu, v, o);
    return v;
}
__device__ __forceinline__ float halfwarpSum(float v){
#pragma unroll
    for (int o = 8; o; o >>= 1) v += __shfl_xor_sync(0xffffffffu, v, o);
    return v;
}
// inclusive scan of 512 floats in smem, 256 row-local threads
__device__ void rowScan512(float* sdata, float* swarp, int rtid){
    float a0 = sdata[2*rtid], a1 = sdata[2*rtid+1];
    float ts = a0 + a1;
    float v = ts;
#pragma unroll
    for (int o = 1; o < 32; o <<= 1){
        float n = __shfl_up_sync(0xffffffffu, v, o);
        if ((rtid & 31) >= o) v += n;
    }
    if ((rtid & 31) == 31) swarp[rtid >> 5] = v;
    __syncthreads();
    if (rtid < 8){
        float w = swarp[rtid];
#pragma unroll
        for (int o = 1; o < 8; o <<= 1){
            float n = __shfl_up_sync(0xffu, w, o);
            if (rtid >= o) w += n;
        }
        swarp[rtid] = w;
    }
    __syncthreads();
    float base = (rtid >= 32) ? swarp[(rtid >> 5) - 1] : 0.f;
    float excl = base + (v - ts);
    sdata[2*rtid]   = excl + a0;
    sdata[2*rtid+1] = excl + a0 + a1;
    __syncthreads();
}

// ---------------- weight transpose ----------------
__global__ void __launch_bounds__(256) transpose_w_kernel(
        const float* Wq1, const float* Wv1, const float* Wo1,
        const float* Wq4, const float* Wk4, const float* Wv4, const float* Wo4){
    int idx = blockIdx.x * 256 + threadIdx.x;
    int w = idx >> 16, e = idx & 65535;
    int d = e >> 8, kk = e & 255;
    const float* src;
    switch (w){
        case 0: src = Wq1; break;  case 1: src = Wv1; break;
        case 2: src = Wo1; break;  case 3: src = Wq4; break;
        case 4: src = Wk4; break;  case 5: src = Wv4; break;
        default: src = Wo4; break;
    }
    g_WT[w*65536 + kk*256 + d] = src[d*256 + kk];
}

// ---------------- proj3: merged 32x64 tile GEMM, double-buffered ----------------
__global__ void __launch_bounds__(256) proj3_kernel(
        const float* Xq, const float* Xse,
        const float* ba, const float* bbp, const float* bc, int single){
    __shared__ float Xs[32][34];
    __shared__ float Ws[32][68];
    int tid = threadIdx.x;
    int row0 = blockIdx.x * 32;
    int n0   = blockIdx.y * 64;
    int z = blockIdx.z;
    const float* X; const float* bias; int wsel, outsel;
    if (single){      X = g_p; bias = ba; wsel = 5; outsel = 3; }
    else if (z == 0){ X = Xq;  bias = ba; wsel = 4; outsel = 2; }
    else if (z == 1){ X = Xq;  bias = bbp; wsel = 0; outsel = 0; }
    else {            X = Xse; bias = bc; wsel = 1; outsel = 1; }
    const float* W = g_WT + (size_t)wsel*65536;

    int lr = tid >> 3;
    int lk = (tid & 7) * 4;
    int wk = tid >> 3;
    int wn = (tid & 7) * 8;

    int tc = tid & 15, tr = tid >> 4;
    ull acc[2][2] = {{0ull,0ull},{0ull,0ull}};

    float4 xv  = *(const float4*)&X[(size_t)(row0 + lr)*256 + lk];
    float4 wv0 = *(const float4*)&W[(size_t)wk*256 + n0 + wn];
    float4 wv1 = *(const float4*)&W[(size_t)wk*256 + n0 + wn + 4];

    for (int kc = 0; kc < 256; kc += 32){
        Xs[lk+0][lr] = xv.x; Xs[lk+1][lr] = xv.y;
        Xs[lk+2][lr] = xv.z; Xs[lk+3][lr] = xv.w;
        *(float4*)&Ws[wk][wn]   = wv0;
        *(float4*)&Ws[wk][wn+4] = wv1;
        __syncthreads();
        if (kc + 32 < 256){
            xv  = *(const float4*)&X[(size_t)(row0 + lr)*256 + kc + 32 + lk];
            wv0 = *(const float4*)&W[(size_t)(kc + 32 + wk)*256 + n0 + wn];
            wv1 = *(const float4*)&W[(size_t)(kc + 32 + wk)*256 + n0 + wn + 4];
        }
#pragma unroll
        for (int k = 0; k < 32; k++){
            float2 a = *(const float2*)&Xs[k][tr*2];
            float4 b = *(const float4*)&Ws[k][tc*4];
            ull b01 = pack2(b.x, b.y), b23 = pack2(b.z, b.w);
            ull a0 = pack2(a.x, a.x), a1 = pack2(a.y, a.y);
            acc[0][0] = ffma2(a0, b01, acc[0][0]);
            acc[0][1] = ffma2(a0, b23, acc[0][1]);
            acc[1][0] = ffma2(a1, b01, acc[1][0]);
            acc[1][1] = ffma2(a1, b23, acc[1][1]);
        }
        __syncthreads();
    }

    int n = n0 + tc*4;
    float4 bb = *(const float4*)&bias[n];
    int h = n >> 5, dk = n & 31;
    float* Yh; float* YT = nullptr;
    switch (outsel){
        case 0: Yh = g_q1; YT = g_q1T; break;
        case 1: Yh = g_v1; break;
        case 2: Yh = g_k4; YT = g_k4T; break;
        default: Yh = g_v4; break;
    }
#pragma unroll
    for (int q = 0; q < 2; q++){
        int row = row0 + tr*2 + q;
        int bidx = row >> 9, s = row & 511;
        float y0,y1,y2,y3;
        unpack2(acc[q][0], y0, y1);
        unpack2(acc[q][1], y2, y3);
        float4 v = make_float4(y0 + bb.x, y1 + bb.y, y2 + bb.z, y3 + bb.w);
        *(float4*)&Yh[(((size_t)(bidx*HH + h)*SS + s)*DKK + dk)] = v;
        if (YT){
            size_t tb = (size_t)(bidx*HH + h)*DKK;
            YT[(tb + dk + 0)*SS + s] = v.x;
            YT[(tb + dk + 1)*SS + s] = v.y;
            YT[(tb + dk + 2)*SS + s] = v.z;
            YT[(tb + dk + 3)*SS + s] = v.w;
        }
    }
}

// ---------------- epi2<RT>: (RT*16)x256 tile GEMM + residual + LayerNorm ----------------
template<int RT>
__global__ void __launch_bounds__(256) epi2_kernel(
        const float* resid, const float* lng, const float* lnb,
        int wsel, const float* bias, int mode, float* dst){
    constexpr int ROWS = RT*16;
    constexpr int XP = (RT == 4) ? 68 : 34;
    __shared__ float Xs[32][XP];
    __shared__ float Ws[32][264];
    int tid = threadIdx.x;
    int row0 = blockIdx.x * ROWS;
    const float* Xsrc = (mode == 0) ? g_att1 : g_out4;
    const float* W = g_WT + (size_t)wsel*65536;
    int tc = tid & 15, tr = tid >> 4;

    ull acc[RT][4][2];
#pragma unroll
    for (int r = 0; r < RT; r++)
#pragma unroll
        for (int cb = 0; cb < 4; cb++){ acc[r][cb][0] = 0ull; acc[r][cb][1] = 0ull; }

    int wk = tid >> 4;
    int wn = (tid & 15) * 16;

    for (int kc = 0; kc < 256; kc += 32){
        float4 x0, x1;
        int xr, xk;
        if (RT == 4){ xr = tid >> 2; xk = (tid & 3) * 8;
            x0 = *(const float4*)&Xsrc[(size_t)(row0 + xr)*256 + kc + xk];
            x1 = *(const float4*)&Xsrc[(size_t)(row0 + xr)*256 + kc + xk + 4];
        } else { xr = tid >> 3; xk = (tid & 7) * 4;
            x0 = *(const float4*)&Xsrc[(size_t)(row0 + xr)*256 + kc + xk];
        }
        float4 w0 = *(const float4*)&W[(size_t)(kc + wk)*256 + wn];
        float4 w1 = *(const float4*)&W[(size_t)(kc + wk)*256 + wn + 4];
        float4 w2 = *(const float4*)&W[(size_t)(kc + wk)*256 + wn + 8];
        float4 w3 = *(const float4*)&W[(size_t)(kc + wk)*256 + wn + 12];
        float4 w4 = *(const float4*)&W[(size_t)(kc + wk + 16)*256 + wn];
        float4 w5 = *(const float4*)&W[(size_t)(kc + wk + 16)*256 + wn + 4];
        float4 w6 = *(const float4*)&W[(size_t)(kc + wk + 16)*256 + wn + 8];
        float4 w7 = *(const float4*)&W[(size_t)(kc + wk + 16)*256 + wn + 12];
        Xs[xk+0][xr] = x0.x; Xs[xk+1][xr] = x0.y; Xs[xk+2][xr] = x0.z; Xs[xk+3][xr] = x0.w;
        if (RT == 4){
            Xs[xk+4][xr] = x1.x; Xs[xk+5][xr] = x1.y; Xs[xk+6][xr] = x1.z; Xs[xk+7][xr] = x1.w;
        }
        *(float4*)&Ws[wk][wn]      = w0;
        *(float4*)&Ws[wk][wn+4]    = w1;
        *(float4*)&Ws[wk][wn+8]    = w2;
        *(float4*)&Ws[wk][wn+12]   = w3;
        *(float4*)&Ws[wk+16][wn]   = w4;
        *(float4*)&Ws[wk+16][wn+4] = w5;
        *(float4*)&Ws[wk+16][wn+8] = w6;
        *(float4*)&Ws[wk+16][wn+12]= w7;
        __syncthreads();
#pragma unroll
        for (int k = 0; k < 32; k++){
            float a[RT];
            if (RT == 4){
                float4 av = *(const float4*)&Xs[k][tr*4];
                a[0]=av.x; a[1]=av.y; a[2]=av.z; a[3]=av.w;
            } else {
                float2 av = *(const float2*)&Xs[k][tr*2];
                a[0]=av.x; a[1]=av.y;
            }
            ull aa[RT];
#pragma unroll
            for (int r = 0; r < RT; r++) aa[r] = pack2(a[r], a[r]);
#pragma unroll
            for (int cb = 0; cb < 4; cb++){
                float4 b = *(const float4*)&Ws[k][cb*64 + tc*4];
                ull b01 = pack2(b.x, b.y), b23 = pack2(b.z, b.w);
#pragma unroll
                for (int r = 0; r < RT; r++){
                    acc[r][cb][0] = ffma2(aa[r], b01, acc[r][cb][0]);
                    acc[r][cb][1] = ffma2(aa[r], b23, acc[r][cb][1]);
                }
            }
        }
        __syncthreads();
    }

    int nb = tc*4;
    float4 bb[4], lg[4], lb[4];
#pragma unroll
    for (int cb = 0; cb < 4; cb++){
        bb[cb] = *(const float4*)&bias[cb*64 + nb];
        lg[cb] = *(const float4*)&lng [cb*64 + nb];
        lb[cb] = *(const float4*)&lnb [cb*64 + nb];
    }
#pragma unroll
    for (int q = 0; q < RT; q++){
        int row = row0 + tr*RT + q;
        float y[16];
#pragma unroll
        for (int cb = 0; cb < 4; cb++){
            float4 rv;
            if (mode == 0) rv = *(const float4*)&resid[(size_t)row*256 + cb*64 + nb];
            else { int kk = (row >> 9) & 15;
                   rv = *(const float4*)&resid[(size_t)kk*256 + cb*64 + nb]; }
            float a0,a1,a2,a3;
            unpack2(acc[q][cb][0], a0, a1);
            unpack2(acc[q][cb][1], a2, a3);
            y[cb*4+0] = a0 + bb[cb].x + rv.x;
            y[cb*4+1] = a1 + bb[cb].y + rv.y;
            y[cb*4+2] = a2 + bb[cb].z + rv.z;
            y[cb*4+3] = a3 + bb[cb].w + rv.w;
        }
        float s = 0.f;
#pragma unroll
        for (int e = 0; e < 16; e++) s += y[e];
        s = halfwarpSum(s);
        float mean = s * (1.f/256.f);
        float vs = 0.f;
#pragma unroll
        for (int e = 0; e < 16; e++){ float t = y[e] - mean; vs += t*t; }
        vs = halfwarpSum(vs);
        float inv = rsqrtf(vs*(1.f/256.f) + 1e-5f);
        size_t base;
        float* out;
        if (mode == 0){ base = (size_t)row*256; out = g_p; }
        else {
            int b = row >> 13, kk = (row >> 9) & 15, s2 = row & 511;
            base = ((size_t)(b*512 + s2)*16 + kk)*256; out = dst;
        }
#pragma unroll
        for (int cb = 0; cb < 4; cb++){
            float4 o;
            o.x = (y[cb*4+0]-mean)*inv*lg[cb].x + lb[cb].x;
            o.y = (y[cb*4+1]-mean)*inv*lg[cb].y + lb[cb].y;
            o.z = (y[cb*4+2]-mean)*inv*lg[cb].z + lb[cb].z;
            o.w = (y[cb*4+3]-mean)*inv*lg[cb].w + lb[cb].w;
            *(float4*)&out[base + cb*64 + nb] = o;
        }
    }
}

// ---------------- r4pre (fused knowproj): score rows + exp prefix sums ----------------
__global__ void __launch_bounds__(256) r4pre_kernel(const float* kp, const float* bq4){
    int idx = blockIdx.x;                 // (b*16+k)*8+h
    int h = idx & 7, bk = idx >> 3, b = bk >> 4, k = bk & 15;
    int tid = threadIdx.x;
    __shared__ float qv[DKK];
    __shared__ float red[8][33];
    __shared__ float sbuf[512];
    __shared__ float sred[8];
    {
        int d = tid & 31, gph = tid >> 5;
        const float* WT = g_WT + 3*65536;
        const float* kr = kp + k*256;
        float a = 0.f;
#pragma unroll 8
        for (int kk = gph*32; kk < gph*32 + 32; kk++)
            a += kr[kk] * WT[kk*256 + h*32 + d];
        red[gph][d] = a;
        __syncthreads();
        if (tid < 32){
            float s = bq4[h*32 + tid];
#pragma unroll
            for (int g2 = 0; g2 < 8; g2++) s += red[g2][tid];
            qv[tid] = s;
        }
        __syncthreads();
    }
    const float* kT = g_k4T + (size_t)(b*HH + h)*DKK*SS;
    int j0 = tid, j1 = tid + 256;
    float r0 = 0.f, r1 = 0.f;
#pragma unroll
    for (int d = 0; d < DKK; d++){
        float q = qv[d];
        r0 += q*kT[d*SS + j0];
        r1 += q*kT[d*SS + j1];
    }
    const float sc = 0.17677669529663687f;  // 1/sqrt(32)
    r0 *= sc; r1 *= sc;
    size_t rb = (size_t)idx*SS;
    g_r4[rb + j0] = r0; g_r4[rb + j1] = r1;
    sbuf[j0] = __expf(r0); sbuf[j1] = __expf(r1);
    __syncthreads();
    rowScan512(sbuf, sred, tid);
    g_P4[rb + j0] = sbuf[j0]; g_P4[rb + j1] = sbuf[j1];
}

// ---------------- attn1: 512 threads, warp-per-row, smem-stashed intermediates ----------
// grid (32 i-tiles of 16 rows, B*H). Measured 57us in R13.
__global__ void __launch_bounds__(512, 2) attn1_kernel(const float* gam, float* qsc){
    int tile = blockIdx.x;
    int bh   = blockIdx.y;          // b*8+h
    int b = bh >> 3, h = bh & 7;
    int tid = threadIdx.x;
    int lane = tid & 31, w = tid >> 5;   // w = 0..15 = row in tile
    int i0 = tile * TIV;

    __shared__ float q_s[TIV][DKK];
    __shared__ float p_s[SS][TIV + 2];

    q_s[w][lane] = g_q1[((size_t)bh*SS + i0 + w)*DKK + lane];
    __syncthreads();

    const float* kT = g_q1T + (size_t)bh*DKK*SS;   // kq_same
    float g = fabsf(gam[h]);
    const float sc = 0.17677669529663687f;

    int ii = w, i = i0 + ii;
    // pass A: scores + exp + running warp prefix; stash score r into p_s
    float PP[16];
    float S = 0.f;
#pragma unroll
    for (int c = 0; c < 16; c++){
        int j = lane + 32*c;
        float r = 0.f, e = 0.f;
        if (32*c <= i){
            if (j <= i){
#pragma unroll
                for (int d = 0; d < DKK; d++)
                    r += q_s[ii][d] * kT[d*SS + j];
                r *= sc;
                e = __expf(r);
            }
            p_s[j][ii] = r;
            float s1 = e;
#pragma unroll
            for (int o = 1; o < 32; o <<= 1){
                float n = __shfl_up_sync(0xffffffffu, s1, o);
                if (lane >= o) s1 += n;
            }
            PP[c] = S + s1;
            S += __shfl_sync(0xffffffffu, s1, 31);
        } else {
            PP[c] = S;
        }
    }
    float invZ = 1.f / S;
    // pass B: second-softmax numerators (read r from p_s, stash f)
    float Zp2 = 0.f;
#pragma unroll
    for (int c = 0; c < 16; c++){
        int j = lane + 32*c;
        float f = 0.f;
        if (j <= i){
            float r = p_s[j][ii];
            float tail = fmaxf(1.f - PP[c]*invZ, 0.f);
            float u = tail * (float)(i - j);
            float eff = fmaxf(__expf(-g*fsqrt_fast(u)), 1e-5f);
            f = __expf(r*eff);
        }
        p_s[j][ii] = f;
        Zp2 += f;
    }
    float inv2 = 1.f / warpSum(Zp2);
    // pass C: normalize, write qsc + p_s
    float* qrow = qsc + ((size_t)bh*SS + i)*SS;
#pragma unroll
    for (int c = 0; c < 16; c++){
        int j = lane + 32*c;
        float p = p_s[j][ii] * inv2;
        qrow[j]    = p;
        p_s[j][ii] = p;
    }
    __syncthreads();

    // PV: 8 warps, 2 rows x 32 d packed
    if (w < 8){
        int d0  = lane;
        int ii0 = w*2;
        ull acc = 0ull;
        const float* vcol = g_v1 + (size_t)bh*SS*DKK + d0;
        int tb = i0 + ii0 + 2;
        int jj = 0;
        for (; jj + 4 <= tb; jj += 4){
#pragma unroll
            for (int u2 = 0; u2 < 4; u2++){
                float v = vcol[(size_t)(jj+u2)*DKK];
                ull pp = *(const ull*)&p_s[jj+u2][ii0];
                acc = ffma2(pp, pack2(v, v), acc);
            }
        }
        for (; jj < tb; jj++){
            float v = vcol[(size_t)jj*DKK];
            ull pp = *(const ull*)&p_s[jj][ii0];
            acc = ffma2(pp, pack2(v, v), acc);
        }
        float a0, a1;
        unpack2(acc, a0, a1);
        float* ob = g_att1 + ((size_t)b*SS + i0 + ii0)*DD + h*DKK + d0;
        ob[0]  = a0;
        ob[DD] = a1;
    }
}

// ---------------- attn4 single-pass (R12 proven version): e in registers ----------------
__global__ void __launch_bounds__(256) attn4_kernel(const float* gam, float* ksc){
    int tile = blockIdx.x;
    int k    = blockIdx.y;
    int bh   = blockIdx.z;
    int b = bh >> 3, h = bh & 7;
    int tid = threadIdx.x;
    int lane = tid & 31, w = tid >> 5;
    int i0 = tile * TIV;

    __shared__ float r_s[SS];
    __shared__ float P_s[SS];
    __shared__ float p_s[SS][TIV + 2];

    size_t rb = ((size_t)((b*NKK + k)*HH + h)) * SS;
    for (int j = tid; j < SS; j += 256){
        r_s[j] = g_r4[rb + j];
        P_s[j] = g_P4[rb + j];
    }
    __syncthreads();

    float g = fabsf(gam[h]);
    size_t kbase0 = (((size_t)(b*HH + h)*SS + i0)*NKK + k)*SS;

    for (int m = 0; m < TIV/8; m++){
        int ii = w + 8*m;
        int i  = i0 + ii;
        float invS1 = (i > 0) ? 1.f / P_s[i-1] : 0.f;
        float fi = (float)i;
        float e16[16];
        float emax = 0.f, Zp = 0.f;
#pragma unroll
        for (int c = 0; c < 16; c++){
            float e = 0.f;
            int j = lane + 32*c;
            if (j < i){
                float r = r_s[j];
                float tail = fmaxf(1.f - P_s[j]*invS1, 0.f);
                float u = tail * (fi - (float)j);
                float eff = fmaxf(__expf(-g*fsqrt_fast(u)), 1e-5f);
                e = __expf(r*eff);
            }
            e16[c] = e;
            emax = fmaxf(emax, e);
            Zp += e;
        }
        float Z  = warpSum(Zp);
        float em = warpMax(emax);
        float C  = (Z > 0.f) ? fminf(Z/em, 5.f)/Z : 0.f;
        float* krow = ksc + kbase0 + (size_t)ii*(NKK*SS);
#pragma unroll
        for (int c = 0; c < 16; c++){
            int j = lane + 32*c;
            float p = e16[c]*C;
            krow[j]    = p;
            p_s[j][ii] = p;
        }
    }
    __syncthreads();

    int d0  = tid & 31;
    int ii0 = (tid >> 5)*2;
    ull acc = 0ull;
    const float* vcol = g_v4 + (size_t)bh*SS*DKK + d0;
    int tb = i0 + ii0 + 2;
    int jj = 0;
    for (; jj + 4 <= tb; jj += 4){
#pragma unroll
        for (int u2 = 0; u2 < 4; u2++){
            float v = vcol[(size_t)(jj+u2)*DKK];
            ull pp = *(const ull*)&p_s[jj+u2][ii0];
            acc = ffma2(pp, pack2(v, v), acc);
        }
    }
    for (; jj < tb; jj++){
        float v = vcol[(size_t)jj*DKK];
        ull pp = *(const ull*)&p_s[jj][ii0];
        acc = ffma2(pp, pack2(v, v), acc);
    }
    float a0, a1;
    unpack2(acc, a0, a1);
    float* ob = g_out4 + ((size_t)(b*NKK + k)*SS + i0 + ii0)*DD + h*DKK + d0;
    ob[0]  = a0;
    ob[DD] = a1;
}

// ---------------- launch ----------------
extern "C" void kernel_launch(void* const* d_in, const int* in_sizes, int n_in,
                              void* d_out, int out_size){
    (void)in_sizes; (void)n_in; (void)out_size;
    const float* q_emb = (const float*)d_in[0];
    const float* s_emb = (const float*)d_in[1];
    const float* Wq1 = (const float*)d_in[5];
    const float* bq1 = (const float*)d_in[6];
    const float* Wv1 = (const float*)d_in[7];
    const float* bv1 = (const float*)d_in[8];
    const float* Wo1 = (const float*)d_in[9];
    const float* bo1 = (const float*)d_in[10];
    const float* gam1= (const float*)d_in[11];
    const float* ln1g= (const float*)d_in[12];
    const float* ln1b= (const float*)d_in[13];
    const float* Wq4 = (const float*)d_in[14];
    const float* bq4 = (const float*)d_in[15];
    const float* Wk4 = (const float*)d_in[16];
    const float* bk4 = (const float*)d_in[17];
    const float* Wv4 = (const float*)d_in[18];
    const float* bv4 = (const float*)d_in[19];
    const float* Wo4 = (const float*)d_in[20];
    const float* bo4 = (const float*)d_in[21];
    const float* gam4= (const float*)d_in[22];
    const float* ln4g= (const float*)d_in[23];
    const float* ln4b= (const float*)d_in[24];
    const float* knowp=(const float*)d_in[25];

    float* out  = (float*)d_out;
    float* z_out = out;                       // [B,S,NK*D]
    float* q_out = out + Z_ELEMS;             // [B,H,S,S]
    float* k_out = out + Z_ELEMS + Q_ELEMS;   // [B,H,S,NK,S]

    transpose_w_kernel<<<1792, 256>>>(Wq1, Wv1, Wo1, Wq4, Wk4, Wv4, Wo4);
    proj3_kernel<<<dim3(32,4,3), 256>>>(q_emb, s_emb, bk4, bq1, bv1, 0);  // k4+q1+v1
    r4pre_kernel<<<256, 256>>>(knowp, bq4);
    attn1_kernel<<<dim3(32, BB*HH), 512>>>(gam1, q_out);                  // 4th: profiled
    epi2_kernel<2><<<32, 256>>>(q_emb, ln1g, ln1b, 2, bo1, 0, nullptr);   // -> g_p
    proj3_kernel<<<dim3(32,4,1), 256>>>(nullptr, nullptr, bv4, nullptr, nullptr, 1); // v4
    attn4_kernel<<<dim3(32, NKK, BB*HH), 256>>>(gam4, k_out);
    epi2_kernel<4><<<256, 256>>>(knowp, ln4g, ln4b, 6, bo4, 1, z_out);    // -> z
}